// round 2
// baseline (speedup 1.0000x reference)
#include <cuda_runtime.h>
#include <math.h>
#include <float.h>

// Problem constants
#define BB  32
#define TT  20
#define CC  512
#define PP  196
#define HH  1024
#define NCC 101

// ---------------- scratch (static device globals; no allocation) ----------------
__device__ float g_sA2[TT * BB * PP];       // precomputed spatial term (T,B,P)
__device__ float g_alphas[TT * BB * PP];    // attention weights (T,B,P)
__device__ float g_h1T[2][HH * BB];         // ping-pong h1, transposed (H,B)
__device__ float g_h2T[2][HH * BB];         // ping-pong h2, transposed (H,B)
__device__ float g_c1T[HH * BB];            // c1 (H,B), in-place per step
__device__ float g_c2T[HH * BB];            // c2 (H,B), in-place per step
__device__ float g_YT[CC * BB];             // context vector, transposed (C,B)
__device__ float g_betas[TT * BB];          // pre-softmax temporal scores
__device__ float g_outs[TT * BB * NCC];     // per-step fc outputs (T,B,NC)

__device__ __forceinline__ float sigm(float x) { return 1.f / (1.f + expf(-x)); }

// ---------------- init: broadcast (1,H) states to (H,B) ----------------
__global__ void init_kernel(const float* __restrict__ h1, const float* __restrict__ c1,
                            const float* __restrict__ h2, const float* __restrict__ c2) {
    int i = blockIdx.x * blockDim.x + threadIdx.x;
    if (i < HH * BB) {
        int h = i >> 5;
        g_h1T[0][i] = h1[h];
        g_c1T[i]    = c1[h];
        g_h2T[0][i] = h2[h];
        g_c2T[i]    = c2[h];
    }
}

// ---------------- precompute sA2[t,b,p] = sum_c videos[b,t,c,p]*W_sC21[c] + b_sC21 ----------------
__global__ void precompute_kernel(const float* __restrict__ videos,
                                  const float* __restrict__ W_sC21,
                                  const float* __restrict__ b_sC21) {
    __shared__ float ws[CC];
    int bt = blockIdx.x;            // b*TT + t
    int b = bt / TT, t = bt % TT;
    for (int i = threadIdx.x; i < CC; i += blockDim.x) ws[i] = W_sC21[i];
    __syncthreads();
    int p = threadIdx.x;
    if (p < PP) {
        const float* vb = videos + (((size_t)b * TT + t) * CC) * PP + p;
        float acc = 0.f;
#pragma unroll 4
        for (int c = 0; c < CC; c++) acc = fmaf(vb[(size_t)c * PP], ws[c], acc);
        g_sA2[(t * BB + b) * PP + p] = acc + b_sC21[0];
    }
}

// ---------------- attention: alpha[t] = softmax_p(h2·W_h2p^T + b + sA2 + spatialBias)
//                  fused: out[t-1] = h2 @ W_fc^T + b_fc  (h2 here == h2 after step t-1)
__global__ void attn_kernel(int t,
                            const float* __restrict__ W_h2p, const float* __restrict__ b_h2p,
                            const float* __restrict__ spatialBias,
                            const float* __restrict__ W_fc, const float* __restrict__ b_fc) {
    __shared__ float h2s[HH];
    __shared__ float lg[256];
    __shared__ float red[256];
    int b = blockIdx.x;
    int tid = threadIdx.x, lane = tid & 31, wid = tid >> 5;
    const float* h2 = g_h2T[t & 1];
    for (int i = tid; i < HH; i += 256) h2s[i] = h2[i * BB + b];
    __syncthreads();

    for (int p = wid; p < PP; p += 8) {
        const float* wr = W_h2p + (size_t)p * HH;
        float s = 0.f;
        for (int h = lane; h < HH; h += 32) s = fmaf(h2s[h], wr[h], s);
        for (int o = 16; o; o >>= 1) s += __shfl_down_sync(0xffffffffu, s, o);
        if (lane == 0)
            lg[p] = s + b_h2p[p] + g_sA2[(t * BB + b) * PP + p] + spatialBias[p];
    }
    __syncthreads();
    float v = (tid < PP) ? lg[tid] : -FLT_MAX;
    red[tid] = v; __syncthreads();
    for (int s = 128; s > 0; s >>= 1) { if (tid < s) red[tid] = fmaxf(red[tid], red[tid + s]); __syncthreads(); }
    float m = red[0]; __syncthreads();
    float e = (tid < PP) ? expf(v - m) : 0.f;
    red[tid] = e; __syncthreads();
    for (int s = 128; s > 0; s >>= 1) { if (tid < s) red[tid] += red[tid + s]; __syncthreads(); }
    float inv = 1.f / red[0];
    if (tid < PP) g_alphas[(t * BB + b) * PP + tid] = e * inv;

    if (t > 0) {  // fc for previous step's hidden state (the h2 we already loaded)
        for (int nc = wid; nc < NCC; nc += 8) {
            const float* wr = W_fc + (size_t)nc * HH;
            float s = 0.f;
            for (int h = lane; h < HH; h += 32) s = fmaf(h2s[h], wr[h], s);
            for (int o = 16; o; o >>= 1) s += __shfl_down_sync(0xffffffffu, s, o);
            if (lane == 0) g_outs[((t - 1) * BB + b) * NCC + nc] = s + b_fc[nc];
        }
    }
}

// ---------------- Y[b,c] = sum_p alpha[b,p]*videos[b,t,c,p]  (store Y^T)
//                  fused beta[t,b] = h2·W_h21 + Y·W_tC21 + consts
__global__ void ybeta_kernel(int t, const float* __restrict__ videos,
                             const float* __restrict__ W_h21, const float* __restrict__ b_h21,
                             const float* __restrict__ W_tC21, const float* __restrict__ b_tC21,
                             const float* __restrict__ temporalBias) {
    __shared__ float al[PP];
    __shared__ float red[256];
    int b = blockIdx.x;
    int tid = threadIdx.x, lane = tid & 31, wid = tid >> 5;
    if (tid < PP) al[tid] = g_alphas[(t * BB + b) * PP + tid];
    __syncthreads();
    const float* vb = videos + (((size_t)b * TT + t) * CC) * PP;
    for (int c = wid; c < CC; c += 8) {
        const float* vr = vb + (size_t)c * PP;
        float s = 0.f;
        for (int p = lane; p < PP; p += 32) s = fmaf(al[p], vr[p], s);
        for (int o = 16; o; o >>= 1) s += __shfl_down_sync(0xffffffffu, s, o);
        if (lane == 0) g_YT[c * BB + b] = s;
    }
    __syncthreads();
    const float* h2 = g_h2T[t & 1];
    float s = 0.f;
    for (int h = tid; h < HH; h += 256) s = fmaf(h2[h * BB + b], W_h21[h], s);
    for (int c = tid; c < CC; c += 256) s = fmaf(g_YT[c * BB + b], W_tC21[c], s);
    red[tid] = s; __syncthreads();
    for (int q = 128; q > 0; q >>= 1) { if (tid < q) red[tid] += red[tid + q]; __syncthreads(); }
    if (tid == 0) g_betas[t * BB + b] = red[0] + b_h21[0] + b_tC21[0] + temporalBias[0];
}

// ---------------- fused LSTM cell: gates = actA@Wih^T + actB@Whh^T + biases; cell update.
// Block: 256 thr = 8 warps; warp = one jj row-group (4 gate rows i/f/g/o), lane = batch.
// Per k: 1 LDS.32 act (conflict-free) + 1 LDS.128 weight (warp-broadcast) + 4 FFMA.
template <int WHICH>
__global__ void lstm_kernel(int t,
                            const float* __restrict__ Wih, const float* __restrict__ Whh,
                            const float* __restrict__ bih, const float* __restrict__ bhh) {
    __shared__ float as_[32][32];     // acts: [k][b]
    __shared__ float ws_[32][36];     // weights: [k][jj*4+g], padded row
    const int tid = threadIdx.x, lane = tid & 31, wid = tid >> 5;
    const int jj0 = blockIdx.x * 8;
    const int rid = tid >> 3, jjg = rid >> 2, gg = rid & 3, koff = (tid & 7) << 2;

    const float* actA; int KA; const float* actB; float* cT; float* hout;
    if (WHICH == 1) { actA = g_YT;              KA = CC; actB = g_h1T[t & 1]; cT = g_c1T; hout = g_h1T[(t + 1) & 1]; }
    else            { actA = g_h1T[(t + 1) & 1]; KA = HH; actB = g_h2T[t & 1]; cT = g_c2T; hout = g_h2T[(t + 1) & 1]; }
    const int KB = HH;

    float acc0 = 0.f, acc1 = 0.f, acc2 = 0.f, acc3 = 0.f;

    for (int phase = 0; phase < 2; phase++) {
        const float* act = phase ? actB : actA;
        const float* W   = phase ? Whh  : Wih;
        const int    K   = phase ? KB   : KA;
        const float* wrow = W + (size_t)(gg * HH + jj0 + jjg) * K + koff;
        const int ntiles = K >> 5;
        // prefetch tile 0 into registers
        float4 a4 = ((const float4*)act)[tid];
        float4 w4 = *(const float4*)wrow;
        for (int tile = 0; tile < ntiles; tile++) {
            __syncthreads();                       // previous tile's compute done
            ((float4*)&as_[0][0])[tid] = a4;
            ws_[koff + 0][jjg * 4 + gg] = w4.x;
            ws_[koff + 1][jjg * 4 + gg] = w4.y;
            ws_[koff + 2][jjg * 4 + gg] = w4.z;
            ws_[koff + 3][jjg * 4 + gg] = w4.w;
            __syncthreads();
            if (tile + 1 < ntiles) {               // prefetch next tile (overlaps compute)
                a4 = ((const float4*)(act + (tile + 1) * 1024))[tid];
                w4 = *(const float4*)(wrow + (tile + 1) * 32);
            }
#pragma unroll
            for (int k = 0; k < 32; k++) {
                float a = as_[k][lane];
                float4 w = *(const float4*)&ws_[k][wid << 2];
                acc0 = fmaf(a, w.x, acc0);
                acc1 = fmaf(a, w.y, acc1);
                acc2 = fmaf(a, w.z, acc2);
                acc3 = fmaf(a, w.w, acc3);
            }
        }
    }

    const int jj = jj0 + wid;
    float gi = acc0 + bih[jj]           + bhh[jj];
    float gf = acc1 + bih[HH + jj]      + bhh[HH + jj];
    float gc = acc2 + bih[2 * HH + jj]  + bhh[2 * HH + jj];
    float go = acc3 + bih[3 * HH + jj]  + bhh[3 * HH + jj];
    const int idx = jj * BB + lane;
    float cn = sigm(gf) * cT[idx] + sigm(gi) * tanhf(gc);
    cT[idx]   = cn;
    hout[idx] = sigm(go) * tanhf(cn);
}

// ---------------- final: fc for t=19, temporal softmax, weighted logits ----------------
__global__ void final_kernel(const float* __restrict__ W_fc, const float* __restrict__ b_fc,
                             float* __restrict__ out_logits, float* __restrict__ out_betasT,
                             int write_betas) {
    __shared__ float h2s[HH];
    __shared__ float bw[TT];
    int b = blockIdx.x;
    int tid = threadIdx.x, lane = tid & 31, wid = tid >> 5;
    const float* h2 = g_h2T[TT & 1];   // buffer 0 after 20 steps
    for (int i = tid; i < HH; i += 128) h2s[i] = h2[i * BB + b];
    __syncthreads();
    for (int nc = wid; nc < NCC; nc += 4) {
        const float* wr = W_fc + (size_t)nc * HH;
        float s = 0.f;
        for (int h = lane; h < HH; h += 32) s = fmaf(h2s[h], wr[h], s);
        for (int o = 16; o; o >>= 1) s += __shfl_down_sync(0xffffffffu, s, o);
        if (lane == 0) g_outs[((TT - 1) * BB + b) * NCC + nc] = s + b_fc[nc];
    }
    __syncthreads();
    if (tid == 0) {
        float m = -FLT_MAX;
        for (int t = 0; t < TT; t++) m = fmaxf(m, g_betas[t * BB + b]);
        float s = 0.f;
        for (int t = 0; t < TT; t++) { float e = expf(g_betas[t * BB + b] - m); bw[t] = e; s += e; }
        float inv = 1.f / s;
        for (int t = 0; t < TT; t++) {
            bw[t] *= inv;
            if (write_betas) out_betasT[b * TT + t] = bw[t];
        }
    }
    __syncthreads();
    for (int nc = tid; nc < NCC; nc += 128) {
        float s = 0.f;
        for (int t = 0; t < TT; t++) s = fmaf(bw[t], g_outs[(t * BB + b) * NCC + nc], s);
        out_logits[b * NCC + nc] = s;
    }
}

// ---------------- launch ----------------
extern "C" void kernel_launch(void* const* d_in, const int* in_sizes, int n_in,
                              void* d_out, int out_size) {
    const float* videos       = (const float*)d_in[0];
    const float* h1           = (const float*)d_in[1];
    const float* c1           = (const float*)d_in[2];
    const float* h2           = (const float*)d_in[3];
    const float* c2           = (const float*)d_in[4];
    const float* spatialBias  = (const float*)d_in[5];
    const float* temporalBias = (const float*)d_in[6];
    const float* W_h2p        = (const float*)d_in[7];
    const float* b_h2p        = (const float*)d_in[8];
    const float* W_sC21       = (const float*)d_in[9];
    const float* b_sC21       = (const float*)d_in[10];
    const float* W_h21        = (const float*)d_in[11];
    const float* b_h21        = (const float*)d_in[12];
    const float* W_tC21       = (const float*)d_in[13];
    const float* b_tC21       = (const float*)d_in[14];
    const float* Wih1         = (const float*)d_in[15];
    const float* Whh1         = (const float*)d_in[16];
    const float* bih1         = (const float*)d_in[17];
    const float* bhh1         = (const float*)d_in[18];
    const float* Wih2         = (const float*)d_in[19];
    const float* Whh2         = (const float*)d_in[20];
    const float* bih2         = (const float*)d_in[21];
    const float* bhh2         = (const float*)d_in[22];
    const float* W_fc         = (const float*)d_in[23];
    const float* b_fc         = (const float*)d_in[24];

    float* out = (float*)d_out;
    const int LOGITS = BB * NCC;        // 3232
    const int ALPHAS = TT * BB * PP;    // 125440
    const int BETAS  = BB * TT;         // 640
    int write_alphas = (out_size >= LOGITS + ALPHAS);
    int write_betas  = (out_size >= LOGITS + ALPHAS + BETAS);

    init_kernel<<<(HH * BB + 255) / 256, 256>>>(h1, c1, h2, c2);
    precompute_kernel<<<BB * TT, 256>>>(videos, W_sC21, b_sC21);

    for (int t = 0; t < TT; t++) {
        attn_kernel<<<BB, 256>>>(t, W_h2p, b_h2p, spatialBias, W_fc, b_fc);
        ybeta_kernel<<<BB, 256>>>(t, videos, W_h21, b_h21, W_tC21, b_tC21, temporalBias);
        lstm_kernel<1><<<HH / 8, 256>>>(t, Wih1, Whh1, bih1, bhh1);
        lstm_kernel<2><<<HH / 8, 256>>>(t, Wih2, Whh2, bih2, bhh2);
    }

    final_kernel<<<BB, 128>>>(W_fc, b_fc, out,
                              write_betas ? (out + LOGITS + ALPHAS) : (float*)0,
                              write_betas);

    if (write_alphas) {
        void* asym = 0;
        cudaGetSymbolAddress(&asym, g_alphas);
        cudaMemcpyAsync(out + LOGITS, asym, sizeof(float) * ALPHAS,
                        cudaMemcpyDeviceToDevice);
    }
}

// round 6
// speedup vs baseline: 2.0820x; 2.0820x over previous
#include <cuda_runtime.h>
#include <math.h>
#include <float.h>

#define BB  32
#define TT  20
#define CC  512
#define PP  196
#define HH  1024
#define NCC 101

typedef unsigned long long ull;

// ---------------- scratch ----------------
__device__ float g_sA2[TT * BB * PP];        // (T,B,P)
__device__ float g_alogits[BB * 208];        // pre-softmax attention logits
__device__ float g_alphas[TT * BB * PP];     // (T,B,P)
__device__ float g_h1T[2][HH * BB];          // (H,B) ping-pong
__device__ float g_h2T[2][HH * BB];          // (H,B) ping-pong
__device__ float g_h2BH[BB * HH];            // (B,H) copy of current h2
__device__ float g_c1T[HH * BB];
__device__ float g_c2T[HH * BB];
__device__ float g_YT[CC * BB];              // (C,B)
__device__ float g_betas[TT * BB];
__device__ float g_outs[TT * BB * NCC];
__device__ float g_part1[3][HH * 4 * BB];    // lstm1 K-split partials
__device__ float g_part2[4][HH * 4 * BB];    // lstm2 K-split partials

__device__ __forceinline__ float sigm(float x) { return 1.f / (1.f + expf(-x)); }

__device__ __forceinline__ void fma2(ull& d, ull a, ull b) {
    asm("fma.rn.f32x2 %0, %1, %2, %0;" : "+l"(d) : "l"(a), "l"(b));
}
__device__ __forceinline__ ull dup2(float a) {
    ull r; asm("mov.b64 %0, {%1, %1};" : "=l"(r) : "f"(a)); return r;
}
__device__ __forceinline__ void unpack2(ull v, float& lo, float& hi) {
    asm("mov.b64 {%0, %1}, %2;" : "=f"(lo), "=f"(hi) : "l"(v));
}

// ---------------- init ----------------
__global__ void init_kernel(const float* __restrict__ h1, const float* __restrict__ c1,
                            const float* __restrict__ h2, const float* __restrict__ c2) {
    int i = blockIdx.x * blockDim.x + threadIdx.x;
    if (i < HH * BB) {
        int h = i >> 5, b = i & 31;
        g_h1T[0][i] = h1[h];
        g_c1T[i]    = c1[h];
        g_h2T[0][i] = h2[h];
        g_c2T[i]    = c2[h];
        g_h2BH[b * HH + h] = h2[h];
    }
}

// ---------------- precompute sA2 ----------------
__global__ void precompute_kernel(const float* __restrict__ videos,
                                  const float* __restrict__ W_sC21,
                                  const float* __restrict__ b_sC21) {
    __shared__ float ws[CC];
    int bt = blockIdx.x;
    int b = bt / TT, t = bt % TT;
    for (int i = threadIdx.x; i < CC; i += blockDim.x) ws[i] = W_sC21[i];
    __syncthreads();
    int p = threadIdx.x;
    if (p < PP) {
        const float* vb = videos + (((size_t)b * TT + t) * CC) * PP + p;
        float acc = 0.f;
#pragma unroll 4
        for (int c = 0; c < CC; c++) acc = fmaf(vb[(size_t)c * PP], ws[c], acc);
        g_sA2[(t * BB + b) * PP + p] = acc + b_sC21[0];
    }
}

// ---------------- attention logits (grid = 32 b x 8 chunks) ----------------
// chunks 0..6: 28 p's each; chunk 7: fc for previous step's output
__global__ void attn_logits_kernel(int t, const float* __restrict__ W_h2p,
                                   const float* __restrict__ b_h2p,
                                   const float* __restrict__ spatialBias,
                                   const float* __restrict__ W_fc,
                                   const float* __restrict__ b_fc) {
    __shared__ float4 h2s[HH / 4];
    int b = blockIdx.x >> 3, chunk = blockIdx.x & 7;
    int tid = threadIdx.x, lane = tid & 31, wid = tid >> 5;
    h2s[tid] = ((const float4*)(g_h2BH + b * HH))[tid];
    __syncthreads();

    if (chunk < 7) {
        for (int sub = wid; sub < 28; sub += 8) {
            int p = chunk * 28 + sub;
            const float4* wr = (const float4*)(W_h2p + (size_t)p * HH);
            float s = 0.f;
            for (int i = lane; i < HH / 4; i += 32) {
                float4 w = wr[i]; float4 a = h2s[i];
                s = fmaf(a.x, w.x, s); s = fmaf(a.y, w.y, s);
                s = fmaf(a.z, w.z, s); s = fmaf(a.w, w.w, s);
            }
            for (int o = 16; o; o >>= 1) s += __shfl_down_sync(0xffffffffu, s, o);
            if (lane == 0)
                g_alogits[b * 208 + p] = s + b_h2p[p] + g_sA2[(t * BB + b) * PP + p] + spatialBias[p];
        }
    } else if (t > 0) {
        for (int nc = wid; nc < NCC; nc += 8) {
            const float4* wr = (const float4*)(W_fc + (size_t)nc * HH);
            float s = 0.f;
            for (int i = lane; i < HH / 4; i += 32) {
                float4 w = wr[i]; float4 a = h2s[i];
                s = fmaf(a.x, w.x, s); s = fmaf(a.y, w.y, s);
                s = fmaf(a.z, w.z, s); s = fmaf(a.w, w.w, s);
            }
            for (int o = 16; o; o >>= 1) s += __shfl_down_sync(0xffffffffu, s, o);
            if (lane == 0) g_outs[((t - 1) * BB + b) * NCC + nc] = s + b_fc[nc];
        }
    }
}

// ---------------- Y gather with fused softmax (grid = 32 b x 8 c-slices) ----------------
// Each block recomputes the 196-wide softmax locally (cheap), removing the
// separate softmax launch from the serial chain. Slice 0 writes g_alphas.
__global__ void ygather_kernel(int t, const float* __restrict__ videos) {
    __shared__ float red[256];
    __shared__ __align__(16) float al[PP];
    int b = blockIdx.x >> 3, cs = blockIdx.x & 7;
    int tid = threadIdx.x, lane = tid & 31, wid = tid >> 5;

    float v = (tid < PP) ? g_alogits[b * 208 + tid] : -FLT_MAX;
    red[tid] = v; __syncthreads();
    for (int s = 128; s > 0; s >>= 1) { if (tid < s) red[tid] = fmaxf(red[tid], red[tid + s]); __syncthreads(); }
    float m = red[0]; __syncthreads();
    float e = (tid < PP) ? expf(v - m) : 0.f;
    red[tid] = e; __syncthreads();
    for (int s = 128; s > 0; s >>= 1) { if (tid < s) red[tid] += red[tid + s]; __syncthreads(); }
    float inv = 1.f / red[0];
    if (tid < PP) {
        float a = e * inv;
        al[tid] = a;
        if (cs == 0) g_alphas[(t * BB + b) * PP + tid] = a;
    }
    __syncthreads();

    const float4* al4 = (const float4*)al;
    const float* vb = videos + ((size_t)(b * TT + t) * CC) * PP;
    int c0 = cs * 64;
    for (int c = c0 + wid; c < c0 + 64; c += 8) {
        const float4* vr = (const float4*)(vb + (size_t)c * PP);
        float s = 0.f;
        for (int i = lane; i < 49; i += 32) {
            float4 vv = vr[i]; float4 a = al4[i];
            s = fmaf(a.x, vv.x, s); s = fmaf(a.y, vv.y, s);
            s = fmaf(a.z, vv.z, s); s = fmaf(a.w, vv.w, s);
        }
        for (int o = 16; o; o >>= 1) s += __shfl_down_sync(0xffffffffu, s, o);
        if (lane == 0) g_YT[c * BB + b] = s;
    }
}

// ---------------- beta (grid = 32) ----------------
__global__ void beta_kernel(int t, const float* __restrict__ W_h21, const float* __restrict__ b_h21,
                            const float* __restrict__ W_tC21, const float* __restrict__ b_tC21,
                            const float* __restrict__ temporalBias) {
    __shared__ float red[128];
    int b = blockIdx.x, tid = threadIdx.x;
    float s = 0.f;
    const float* h2 = g_h2BH + b * HH;
    for (int h = tid; h < HH; h += 128) s = fmaf(h2[h], W_h21[h], s);
    for (int c = tid; c < CC; c += 128) s = fmaf(g_YT[c * BB + b], W_tC21[c], s);
    red[tid] = s; __syncthreads();
    for (int q = 64; q > 0; q >>= 1) { if (tid < q) red[tid] += red[tid + q]; __syncthreads(); }
    if (tid == 0) g_betas[t * BB + b] = red[0] + b_h21[0] + b_tC21[0] + temporalBias[0];
}

// ---------------- LSTM gate GEMM, K-split, f32x2 ----------------
// grid = (64 row-blocks of 16 jj, nseg K-segments of 512). Block: 128 thr / 4 warps.
// Warp w owns jj = jjb + w*4 .. +3, all 4 gates, lane = batch.
// part[seg][(jj*4+g)*32 + b]
__global__ __launch_bounds__(128) void lstm_gemm_kernel(
    const float* __restrict__ actA, const float* __restrict__ WA, int KA,
    const float* __restrict__ actB, const float* __restrict__ WB,
    float* __restrict__ part) {
    __shared__ float as_[32][BB];
    __shared__ float ws_[32][68];
    const int tid = threadIdx.x, lane = tid & 31, wid = tid >> 5;
    const int jjb = blockIdx.x * 16;
    const int seg = blockIdx.y;
    const int nA = KA >> 9;

    const float* act; const float* W; int k0, Kw;
    if (seg < nA) { act = actA; W = WA; k0 = seg << 9; Kw = KA; }
    else          { act = actB; W = WB; k0 = (seg - nA) << 9; Kw = HH; }

    // staging role: entry e = locjj*4 + g  (64 entries), kh = which 16-k half
    const int e = tid & 63;
    const int kh = tid >> 6;
    const int g = e & 3;
    const int locjj = e >> 2;
    const float* wsrc = W + (size_t)(g * HH + jjb + locjj) * Kw + k0 + kh * 16;
    const float4* asrc = (const float4*)(act + (size_t)k0 * BB);

    ull acc[8];
#pragma unroll
    for (int i = 0; i < 8; i++) acc[i] = 0ull;
    const int rowbase = wid * 16;

    float4 w4[4], a4[2];
#pragma unroll
    for (int i = 0; i < 4; i++) w4[i] = ((const float4*)wsrc)[i];
    a4[0] = asrc[tid]; a4[1] = asrc[tid + 128];

    const int ntiles = 512 / 32;
    for (int tile = 0; tile < ntiles; tile++) {
        __syncthreads();
        ((float4*)as_)[tid] = a4[0];
        ((float4*)as_)[tid + 128] = a4[1];
#pragma unroll
        for (int i = 0; i < 4; i++) {
            ws_[kh * 16 + 4 * i + 0][e] = w4[i].x;
            ws_[kh * 16 + 4 * i + 1][e] = w4[i].y;
            ws_[kh * 16 + 4 * i + 2][e] = w4[i].z;
            ws_[kh * 16 + 4 * i + 3][e] = w4[i].w;
        }
        __syncthreads();
        if (tile + 1 < ntiles) {
            const float4* wn = (const float4*)(wsrc + (tile + 1) * 32);
#pragma unroll
            for (int i = 0; i < 4; i++) w4[i] = wn[i];
            const float4* an = asrc + (tile + 1) * 256;
            a4[0] = an[tid]; a4[1] = an[tid + 128];
        }
#pragma unroll
        for (int k = 0; k < 32; k++) {
            ull a2 = dup2(as_[k][lane]);
#pragma unroll
            for (int j = 0; j < 4; j++) {
                ulonglong2 wv = *(const ulonglong2*)&ws_[k][rowbase + 4 * j];
                fma2(acc[2 * j], a2, wv.x);
                fma2(acc[2 * j + 1], a2, wv.y);
            }
        }
    }

#pragma unroll
    for (int j = 0; j < 4; j++) {
        float f0, f1, f2, f3;
        unpack2(acc[2 * j], f0, f1);
        unpack2(acc[2 * j + 1], f2, f3);
        int jj = jjb + wid * 4 + j;
        // FIX: include the K-segment offset (was missing -> all segments raced
        // into segment 0 and the epilogue summed garbage).
        float* dst = part + (size_t)seg * (HH * 4 * BB) + (size_t)jj * 4 * BB + lane;
        dst[0 * BB] = f0; dst[1 * BB] = f1; dst[2 * BB] = f2; dst[3 * BB] = f3;
    }
}

// ---------------- cell epilogue: combine partials + LSTM cell update ----------------
__global__ void cell_epilogue(const float* __restrict__ part, int nseg,
                              const float* __restrict__ bih, const float* __restrict__ bhh,
                              float* __restrict__ cT, float* __restrict__ hT,
                              float* __restrict__ hBH) {
    int i = blockIdx.x * 256 + threadIdx.x;     // 0 .. 32767
    int jj = i >> 5, b = i & 31;
    float gv[4];
#pragma unroll
    for (int g = 0; g < 4; g++) {
        float s = bih[g * HH + jj] + bhh[g * HH + jj];
        for (int sg = 0; sg < 4; sg++)
            if (sg < nseg) s += part[(size_t)sg * (HH * 4 * BB) + (jj * 4 + g) * BB + b];
        gv[g] = s;
    }
    int idx = jj * BB + b;
    float cn = sigm(gv[1]) * cT[idx] + sigm(gv[0]) * tanhf(gv[2]);
    float hn = sigm(gv[3]) * tanhf(cn);
    cT[idx] = cn;
    hT[idx] = hn;
    if (hBH) hBH[b * HH + jj] = hn;
}

// ---------------- final: fc(t=19), temporal softmax, weighted logits ----------------
__global__ void final_kernel(const float* __restrict__ W_fc, const float* __restrict__ b_fc,
                             float* __restrict__ out_logits, float* __restrict__ out_betasT,
                             int write_betas) {
    __shared__ float h2s[HH];
    __shared__ float bw[TT];
    int b = blockIdx.x;
    int tid = threadIdx.x, lane = tid & 31, wid = tid >> 5;
    for (int i = tid; i < HH; i += 128) h2s[i] = g_h2BH[b * HH + i];
    __syncthreads();
    for (int nc = wid; nc < NCC; nc += 4) {
        const float* wr = W_fc + (size_t)nc * HH;
        float s = 0.f;
        for (int h = lane; h < HH; h += 32) s = fmaf(h2s[h], wr[h], s);
        for (int o = 16; o; o >>= 1) s += __shfl_down_sync(0xffffffffu, s, o);
        if (lane == 0) g_outs[((TT - 1) * BB + b) * NCC + nc] = s + b_fc[nc];
    }
    __syncthreads();
    if (tid == 0) {
        float m = -FLT_MAX;
        for (int t = 0; t < TT; t++) m = fmaxf(m, g_betas[t * BB + b]);
        float s = 0.f;
        for (int t = 0; t < TT; t++) { float e = expf(g_betas[t * BB + b] - m); bw[t] = e; s += e; }
        float inv = 1.f / s;
        for (int t = 0; t < TT; t++) {
            bw[t] *= inv;
            if (write_betas) out_betasT[b * TT + t] = bw[t];
        }
    }
    __syncthreads();
    for (int nc = tid; nc < NCC; nc += 128) {
        float s = 0.f;
        for (int t = 0; t < TT; t++) s = fmaf(bw[t], g_outs[(t * BB + b) * NCC + nc], s);
        out_logits[b * NCC + nc] = s;
    }
}

// ---------------- launch ----------------
extern "C" void kernel_launch(void* const* d_in, const int* in_sizes, int n_in,
                              void* d_out, int out_size) {
    const float* videos       = (const float*)d_in[0];
    const float* h1           = (const float*)d_in[1];
    const float* c1           = (const float*)d_in[2];
    const float* h2           = (const float*)d_in[3];
    const float* c2           = (const float*)d_in[4];
    const float* spatialBias  = (const float*)d_in[5];
    const float* temporalBias = (const float*)d_in[6];
    const float* W_h2p        = (const float*)d_in[7];
    const float* b_h2p        = (const float*)d_in[8];
    const float* W_sC21       = (const float*)d_in[9];
    const float* b_sC21       = (const float*)d_in[10];
    const float* W_h21        = (const float*)d_in[11];
    const float* b_h21        = (const float*)d_in[12];
    const float* W_tC21       = (const float*)d_in[13];
    const float* b_tC21       = (const float*)d_in[14];
    const float* Wih1         = (const float*)d_in[15];
    const float* Whh1         = (const float*)d_in[16];
    const float* bih1         = (const float*)d_in[17];
    const float* bhh1         = (const float*)d_in[18];
    const float* Wih2         = (const float*)d_in[19];
    const float* Whh2         = (const float*)d_in[20];
    const float* bih2         = (const float*)d_in[21];
    const float* bhh2         = (const float*)d_in[22];
    const float* W_fc         = (const float*)d_in[23];
    const float* b_fc         = (const float*)d_in[24];

    float* out = (float*)d_out;
    const int LOGITS = BB * NCC;
    const int ALPHAS = TT * BB * PP;
    const int BETAS  = BB * TT;
    int write_alphas = (out_size >= LOGITS + ALPHAS);
    int write_betas  = (out_size >= LOGITS + ALPHAS + BETAS);

    float *p1, *p2, *h1T0, *h1T1, *h2T0, *h2T1, *c1T, *c2T, *h2BH, *YT;
    cudaGetSymbolAddress((void**)&p1, g_part1);
    cudaGetSymbolAddress((void**)&p2, g_part2);
    cudaGetSymbolAddress((void**)&h1T0, g_h1T);
    cudaGetSymbolAddress((void**)&h2T0, g_h2T);
    cudaGetSymbolAddress((void**)&c1T, g_c1T);
    cudaGetSymbolAddress((void**)&c2T, g_c2T);
    cudaGetSymbolAddress((void**)&h2BH, g_h2BH);
    cudaGetSymbolAddress((void**)&YT, g_YT);
    h1T1 = h1T0 + HH * BB;
    h2T1 = h2T0 + HH * BB;

    init_kernel<<<(HH * BB + 255) / 256, 256>>>(h1, c1, h2, c2);
    precompute_kernel<<<BB * TT, 256>>>(videos, W_sC21, b_sC21);

    for (int t = 0; t < TT; t++) {
        float* h1_in  = (t & 1) ? h1T1 : h1T0;
        float* h1_out = (t & 1) ? h1T0 : h1T1;
        float* h2_in  = (t & 1) ? h2T1 : h2T0;
        float* h2_out = (t & 1) ? h2T0 : h2T1;

        attn_logits_kernel<<<BB * 8, 256>>>(t, W_h2p, b_h2p, spatialBias, W_fc, b_fc);
        ygather_kernel<<<BB * 8, 256>>>(t, videos);
        beta_kernel<<<BB, 128>>>(t, W_h21, b_h21, W_tC21, b_tC21, temporalBias);

        dim3 grid1(64, 3);
        lstm_gemm_kernel<<<grid1, 128>>>(YT, Wih1, CC, h1_in, Whh1, p1);
        cell_epilogue<<<128, 256>>>(p1, 3, bih1, bhh1, c1T, h1_out, (float*)0);
        dim3 grid2(64, 4);
        lstm_gemm_kernel<<<grid2, 128>>>(h1_out, Wih2, HH, h2_in, Whh2, p2);
        cell_epilogue<<<128, 256>>>(p2, 4, bih2, bhh2, c2T, h2_out, h2BH);
    }

    final_kernel<<<BB, 128>>>(W_fc, b_fc, out,
                              write_betas ? (out + LOGITS + ALPHAS) : (float*)0,
                              write_betas);

    if (write_alphas) {
        void* asym = 0;
        cudaGetSymbolAddress(&asym, g_alphas);
        cudaMemcpyAsync(out + LOGITS, asym, sizeof(float) * ALPHAS,
                        cudaMemcpyDeviceToDevice);
    }
}

// round 10
// speedup vs baseline: 2.5476x; 1.2236x over previous
#include <cuda_runtime.h>
#include <math.h>
#include <float.h>

#define BB  32
#define TT  20
#define CC  512
#define PP  196
#define HH  1024
#define NCC 101

typedef unsigned long long ull;

// ---------------- scratch ----------------
__device__ float g_sA2[TT * BB * PP];
__device__ float g_alogits[BB * 208];
__device__ float g_alphas[TT * BB * PP];
__device__ float g_h1T[2][HH * BB];
__device__ float g_h2T[2][HH * BB];
__device__ float g_h2BH[BB * HH];
__device__ float g_c1T[HH * BB];
__device__ float g_c2T[HH * BB];
__device__ float g_YT[CC * BB];
__device__ float g_betas[TT * BB];
__device__ float g_outs[TT * BB * NCC];
__device__ float g_part1[3][HH * 4 * BB];
__device__ float g_part2[4][HH * 4 * BB];

// software grid barrier state
__device__ volatile unsigned g_bar_gen;
__device__ unsigned g_bar_cnt;

__device__ __forceinline__ float sigm(float x) { return 1.f / (1.f + expf(-x)); }

__device__ __forceinline__ void fma2(ull& d, ull a, ull b) {
    asm("fma.rn.f32x2 %0, %1, %2, %0;" : "+l"(d) : "l"(a), "l"(b));
}
__device__ __forceinline__ ull dup2(float a) {
    ull r; asm("mov.b64 %0, {%1, %1};" : "=l"(r) : "f"(a)); return r;
}
__device__ __forceinline__ void unpack2(ull v, float& lo, float& hi) {
    asm("mov.b64 {%0, %1}, %2;" : "=f"(lo), "=f"(hi) : "l"(v));
}

// sense-reversal grid barrier: all blocks must call it the same number of times
__device__ __forceinline__ void grid_sync_dev() {
    __syncthreads();
    if (threadIdx.x == 0) {
        unsigned gen = g_bar_gen;          // ticket read BEFORE arrive (volatile)
        __threadfence();                   // release prior writes (gpu scope)
        if (atomicAdd(&g_bar_cnt, 1u) == gridDim.x - 1) {
            g_bar_cnt = 0;
            __threadfence();
            g_bar_gen = gen + 1;           // release
        } else {
            while (g_bar_gen == gen) { }   // volatile spin (L2)
            __threadfence();               // acquire: invalidate L1 before reads
        }
    }
    __syncthreads();
}

// ---------------- LSTM gate GEMM half-block body (128 threads) ----------------
// subvb: (jjblock 0..63) | (seg<<6). Identical structure for both halves so the
// block-wide __syncthreads inside stays aligned.
__device__ __forceinline__ void gemm_half(
    int htid,
    const float* __restrict__ actA, const float* __restrict__ WA, int KA,
    const float* __restrict__ actB, const float* __restrict__ WB,
    float* __restrict__ part, int subvb,
    float (*as_)[BB], float (*ws_)[68])
{
    const int lane = htid & 31, wid = htid >> 5;
    const int jjb = (subvb & 63) * 16;
    const int seg = subvb >> 6;
    const int nA = KA >> 9;

    const float* act; const float* W; int k0, Kw;
    if (seg < nA) { act = actA; W = WA; k0 = seg << 9; Kw = KA; }
    else          { act = actB; W = WB; k0 = (seg - nA) << 9; Kw = HH; }

    const int e = htid & 63;
    const int kh = htid >> 6;
    const int g = e & 3;
    const int locjj = e >> 2;
    const float* wsrc = W + (size_t)(g * HH + jjb + locjj) * Kw + k0 + kh * 16;
    const float4* asrc = (const float4*)(act + (size_t)k0 * BB);

    ull acc[8];
#pragma unroll
    for (int i = 0; i < 8; i++) acc[i] = 0ull;
    const int rowbase = wid * 16;

    float4 w4[4], a4[2];
#pragma unroll
    for (int i = 0; i < 4; i++) w4[i] = ((const float4*)wsrc)[i];
    a4[0] = asrc[htid]; a4[1] = asrc[htid + 128];

    const int ntiles = 512 / 32;
    for (int tile = 0; tile < ntiles; tile++) {
        __syncthreads();
        ((float4*)as_)[htid] = a4[0];
        ((float4*)as_)[htid + 128] = a4[1];
#pragma unroll
        for (int i = 0; i < 4; i++) {
            ws_[kh * 16 + 4 * i + 0][e] = w4[i].x;
            ws_[kh * 16 + 4 * i + 1][e] = w4[i].y;
            ws_[kh * 16 + 4 * i + 2][e] = w4[i].z;
            ws_[kh * 16 + 4 * i + 3][e] = w4[i].w;
        }
        __syncthreads();
        if (tile + 1 < ntiles) {
            const float4* wn = (const float4*)(wsrc + (tile + 1) * 32);
#pragma unroll
            for (int i = 0; i < 4; i++) w4[i] = wn[i];
            const float4* an = asrc + (tile + 1) * 256;
            a4[0] = an[htid]; a4[1] = an[htid + 128];
        }
#pragma unroll
        for (int k = 0; k < 32; k++) {
            ull a2 = dup2(as_[k][lane]);
#pragma unroll
            for (int j = 0; j < 4; j++) {
                ulonglong2 wv = *(const ulonglong2*)&ws_[k][rowbase + 4 * j];
                fma2(acc[2 * j], a2, wv.x);
                fma2(acc[2 * j + 1], a2, wv.y);
            }
        }
    }

#pragma unroll
    for (int j = 0; j < 4; j++) {
        float f0, f1, f2, f3;
        unpack2(acc[2 * j], f0, f1);
        unpack2(acc[2 * j + 1], f2, f3);
        int jj = jjb + wid * 4 + j;
        float* dst = part + (size_t)seg * (HH * 4 * BB) + (size_t)jj * 4 * BB + lane;
        dst[0 * BB] = f0; dst[1 * BB] = f1; dst[2 * BB] = f2; dst[3 * BB] = f3;
    }
}

// ---------------- the persistent mega-kernel ----------------
__global__ void __launch_bounds__(256, 1) mega_kernel(
    const float* __restrict__ videos,
    const float* __restrict__ h1, const float* __restrict__ c1,
    const float* __restrict__ h2, const float* __restrict__ c2,
    const float* __restrict__ spatialBias, const float* __restrict__ temporalBias,
    const float* __restrict__ W_h2p, const float* __restrict__ b_h2p,
    const float* __restrict__ W_sC21, const float* __restrict__ b_sC21,
    const float* __restrict__ W_h21, const float* __restrict__ b_h21,
    const float* __restrict__ W_tC21, const float* __restrict__ b_tC21,
    const float* __restrict__ Wih1, const float* __restrict__ Whh1,
    const float* __restrict__ bih1, const float* __restrict__ bhh1,
    const float* __restrict__ Wih2, const float* __restrict__ Whh2,
    const float* __restrict__ bih2, const float* __restrict__ bhh2,
    const float* __restrict__ W_fc, const float* __restrict__ b_fc,
    float* __restrict__ out, int write_alphas, int write_betas)
{
    __shared__ float  s_as[2][32][BB];
    __shared__ float  s_ws[2][32][68];
    __shared__ float4 s_h2[HH / 4];
    __shared__ float  s_red[256];
    __shared__ __align__(16) float s_al[PP];
    __shared__ float  s_wsc[CC];
    __shared__ float  s_bw[TT];

    const int tid = threadIdx.x, lane = tid & 31, wid = tid >> 5;
    const int NBK = gridDim.x;
    const int half = tid >> 7, htid = tid & 127;

    const int LOGITS = BB * NCC;
    const int ALPHAS = TT * BB * PP;

    // ---- init: broadcast states ----
    for (int vb = blockIdx.x; vb < 128; vb += NBK) {
        int i = vb * 256 + tid;
        int h = i >> 5, b = i & 31;
        g_h1T[0][i] = h1[h];
        g_c1T[i]    = c1[h];
        g_h2T[0][i] = h2[h];
        g_c2T[i]    = c2[h];
        g_h2BH[b * HH + h] = h2[h];
    }

    // ---- precompute sA2 (W_sC21 loaded once) ----
    for (int i = tid; i < CC; i += 256) s_wsc[i] = W_sC21[i];
    __syncthreads();
    for (int vb = blockIdx.x; vb < BB * TT; vb += NBK) {
        int b = vb / TT, t = vb % TT;
        if (tid < PP) {
            const float* vbp = videos + (((size_t)b * TT + t) * CC) * PP + tid;
            float acc = 0.f;
#pragma unroll 4
            for (int c = 0; c < CC; c++) acc = fmaf(vbp[(size_t)c * PP], s_wsc[c], acc);
            g_sA2[(t * BB + b) * PP + tid] = acc + b_sC21[0];
        }
    }
    grid_sync_dev();

    for (int t = 0; t < TT; t++) {
        float* h1_in  = g_h1T[t & 1];
        float* h1_out = g_h1T[(t + 1) & 1];
        float* h2_in  = g_h2T[t & 1];
        float* h2_out = g_h2T[(t + 1) & 1];

        // ---- Phase A: attention logits + fc(prev h2) ----
        for (int vb = blockIdx.x; vb < 256; vb += NBK) {
            int b = vb >> 3, chunk = vb & 7;
            s_h2[tid] = ((const float4*)(g_h2BH + b * HH))[tid];
            __syncthreads();
            if (chunk < 7) {
                for (int sub = wid; sub < 28; sub += 8) {
                    int p = chunk * 28 + sub;
                    const float4* wr = (const float4*)(W_h2p + (size_t)p * HH);
                    float s = 0.f;
                    for (int i = lane; i < HH / 4; i += 32) {
                        float4 w = wr[i]; float4 a = s_h2[i];
                        s = fmaf(a.x, w.x, s); s = fmaf(a.y, w.y, s);
                        s = fmaf(a.z, w.z, s); s = fmaf(a.w, w.w, s);
                    }
                    for (int o = 16; o; o >>= 1) s += __shfl_down_sync(0xffffffffu, s, o);
                    if (lane == 0)
                        g_alogits[b * 208 + p] = s + b_h2p[p] + g_sA2[(t * BB + b) * PP + p] + spatialBias[p];
                }
            } else if (t > 0) {
                for (int nc = wid; nc < NCC; nc += 8) {
                    const float4* wr = (const float4*)(W_fc + (size_t)nc * HH);
                    float s = 0.f;
                    for (int i = lane; i < HH / 4; i += 32) {
                        float4 w = wr[i]; float4 a = s_h2[i];
                        s = fmaf(a.x, w.x, s); s = fmaf(a.y, w.y, s);
                        s = fmaf(a.z, w.z, s); s = fmaf(a.w, w.w, s);
                    }
                    for (int o = 16; o; o >>= 1) s += __shfl_down_sync(0xffffffffu, s, o);
                    if (lane == 0) g_outs[((t - 1) * BB + b) * NCC + nc] = s + b_fc[nc];
                }
            }
            __syncthreads();
        }
        grid_sync_dev();

        // ---- Phase B: softmax (recomputed per vb) + Y gather ----
        for (int vb = blockIdx.x; vb < 512; vb += NBK) {
            int b = vb >> 4, cs = vb & 15;
            float v = (tid < PP) ? g_alogits[b * 208 + tid] : -FLT_MAX;
            s_red[tid] = v; __syncthreads();
            for (int s = 128; s > 0; s >>= 1) { if (tid < s) s_red[tid] = fmaxf(s_red[tid], s_red[tid + s]); __syncthreads(); }
            float m = s_red[0]; __syncthreads();
            float e = (tid < PP) ? expf(v - m) : 0.f;
            s_red[tid] = e; __syncthreads();
            for (int s = 128; s > 0; s >>= 1) { if (tid < s) s_red[tid] += s_red[tid + s]; __syncthreads(); }
            float inv = 1.f / s_red[0];
            if (tid < PP) {
                float a = e * inv;
                s_al[tid] = a;
                if (cs == 0) g_alphas[(t * BB + b) * PP + tid] = a;
            }
            __syncthreads();
            const float4* al4 = (const float4*)s_al;
            const float* vbp = videos + ((size_t)(b * TT + t) * CC) * PP;
            int c0 = cs * 32;
            for (int c = c0 + wid; c < c0 + 32; c += 8) {
                const float4* vr = (const float4*)(vbp + (size_t)c * PP);
                float s = 0.f;
                for (int i = lane; i < 49; i += 32) {
                    float4 vv = vr[i]; float4 a = al4[i];
                    s = fmaf(a.x, vv.x, s); s = fmaf(a.y, vv.y, s);
                    s = fmaf(a.z, vv.z, s); s = fmaf(a.w, vv.w, s);
                }
                for (int o = 16; o; o >>= 1) s += __shfl_down_sync(0xffffffffu, s, o);
                if (lane == 0) g_YT[c * BB + b] = s;
            }
            __syncthreads();
        }
        grid_sync_dev();

        // ---- Phase D: gemm1 (96 block-vbs, 2 halves each) + beta (vb 96) ----
        for (int vb = blockIdx.x; vb < 97; vb += NBK) {
            if (vb < 96) {
                gemm_half(htid, g_YT, Wih1, CC, h1_in, Whh1,
                          &g_part1[0][0], vb * 2 + half, s_as[half], s_ws[half]);
            } else {
                // beta: warp w handles b = r*8 + w
                for (int r = 0; r < 4; r++) {
                    int b = r * 8 + wid;
                    const float* h2r = g_h2BH + b * HH;
                    float s = 0.f;
                    for (int h = lane; h < HH; h += 32) s = fmaf(h2r[h], W_h21[h], s);
                    for (int c = lane; c < CC; c += 32) s = fmaf(g_YT[c * BB + b], W_tC21[c], s);
                    for (int o = 16; o; o >>= 1) s += __shfl_down_sync(0xffffffffu, s, o);
                    if (lane == 0)
                        g_betas[t * BB + b] = s + b_h21[0] + b_tC21[0] + temporalBias[0];
                }
            }
        }
        grid_sync_dev();

        // ---- Phase E: epilogue cell 1 ----
        for (int vb = blockIdx.x; vb < 128; vb += NBK) {
            int i = vb * 256 + tid;
            int jj = i >> 5, b = i & 31;
            float gv[4];
#pragma unroll
            for (int g = 0; g < 4; g++) {
                float s = bih1[g * HH + jj] + bhh1[g * HH + jj];
#pragma unroll
                for (int sg = 0; sg < 3; sg++)
                    s += g_part1[sg][(jj * 4 + g) * BB + b];
                gv[g] = s;
            }
            int idx = jj * BB + b;
            float cn = sigm(gv[1]) * g_c1T[idx] + sigm(gv[0]) * tanhf(gv[2]);
            g_c1T[idx] = cn;
            h1_out[idx] = sigm(gv[3]) * tanhf(cn);
        }
        grid_sync_dev();

        // ---- Phase F: gemm2 (128 block-vbs) ----
        for (int vb = blockIdx.x; vb < 128; vb += NBK) {
            gemm_half(htid, h1_out, Wih2, HH, h2_in, Whh2,
                      &g_part2[0][0], vb * 2 + half, s_as[half], s_ws[half]);
        }
        grid_sync_dev();

        // ---- Phase G: epilogue cell 2 (+ h2BH update) ----
        for (int vb = blockIdx.x; vb < 128; vb += NBK) {
            int i = vb * 256 + tid;
            int jj = i >> 5, b = i & 31;
            float gv[4];
#pragma unroll
            for (int g = 0; g < 4; g++) {
                float s = bih2[g * HH + jj] + bhh2[g * HH + jj];
#pragma unroll
                for (int sg = 0; sg < 4; sg++)
                    s += g_part2[sg][(jj * 4 + g) * BB + b];
                gv[g] = s;
            }
            int idx = jj * BB + b;
            float cn = sigm(gv[1]) * g_c2T[idx] + sigm(gv[0]) * tanhf(gv[2]);
            float hn = sigm(gv[3]) * tanhf(cn);
            g_c2T[idx] = cn;
            h2_out[idx] = hn;
            g_h2BH[b * HH + jj] = hn;
        }
        grid_sync_dev();
    }

    // ---- Final: fc(t=19) + temporal softmax + weighted logits; alpha copy ----
    {
        float* h2f = (float*)s_h2;       // reuse 4KB
        const int NVB_FIN = 32 + (31360 + 255) / 256;   // 32 + 123
        for (int vb = blockIdx.x; vb < NVB_FIN; vb += NBK) {
            if (vb < 32) {
                int b = vb;
                for (int i = tid; i < HH; i += 256) h2f[i] = g_h2BH[b * HH + i];
                __syncthreads();
                for (int nc = wid; nc < NCC; nc += 8) {
                    const float* wr = W_fc + (size_t)nc * HH;
                    float s = 0.f;
                    for (int h = lane; h < HH; h += 32) s = fmaf(h2f[h], wr[h], s);
                    for (int o = 16; o; o >>= 1) s += __shfl_down_sync(0xffffffffu, s, o);
                    if (lane == 0) g_outs[((TT - 1) * BB + b) * NCC + nc] = s + b_fc[nc];
                }
                __syncthreads();
                if (tid == 0) {
                    float m = -FLT_MAX;
                    for (int tt = 0; tt < TT; tt++) m = fmaxf(m, g_betas[tt * BB + b]);
                    float s = 0.f;
                    for (int tt = 0; tt < TT; tt++) { float e = expf(g_betas[tt * BB + b] - m); s_bw[tt] = e; s += e; }
                    float inv = 1.f / s;
                    for (int tt = 0; tt < TT; tt++) {
                        s_bw[tt] *= inv;
                        if (write_betas) out[LOGITS + ALPHAS + b * TT + tt] = s_bw[tt];
                    }
                }
                __syncthreads();
                for (int nc = tid; nc < NCC; nc += 256) {
                    float s = 0.f;
                    for (int tt = 0; tt < TT; tt++) s = fmaf(s_bw[tt], g_outs[(tt * BB + b) * NCC + nc], s);
                    out[b * NCC + nc] = s;
                }
                __syncthreads();
            } else if (write_alphas) {
                int i = (vb - 32) * 256 + tid;       // float4 index
                if (i < 31360)
                    ((float4*)(out + LOGITS))[i] = ((const float4*)g_alphas)[i];
            }
        }
    }
}

// ---------------- launch: ONE persistent kernel ----------------
extern "C" void kernel_launch(void* const* d_in, const int* in_sizes, int n_in,
                              void* d_out, int out_size) {
    const float* videos       = (const float*)d_in[0];
    const float* h1           = (const float*)d_in[1];
    const float* c1           = (const float*)d_in[2];
    const float* h2           = (const float*)d_in[3];
    const float* c2           = (const float*)d_in[4];
    const float* spatialBias  = (const float*)d_in[5];
    const float* temporalBias = (const float*)d_in[6];
    const float* W_h2p        = (const float*)d_in[7];
    const float* b_h2p        = (const float*)d_in[8];
    const float* W_sC21       = (const float*)d_in[9];
    const float* b_sC21       = (const float*)d_in[10];
    const float* W_h21        = (const float*)d_in[11];
    const float* b_h21        = (const float*)d_in[12];
    const float* W_tC21       = (const float*)d_in[13];
    const float* b_tC21       = (const float*)d_in[14];
    const float* Wih1         = (const float*)d_in[15];
    const float* Whh1         = (const float*)d_in[16];
    const float* bih1         = (const float*)d_in[17];
    const float* bhh1         = (const float*)d_in[18];
    const float* Wih2         = (const float*)d_in[19];
    const float* Whh2         = (const float*)d_in[20];
    const float* bih2         = (const float*)d_in[21];
    const float* bhh2         = (const float*)d_in[22];
    const float* W_fc         = (const float*)d_in[23];
    const float* b_fc         = (const float*)d_in[24];

    float* out = (float*)d_out;
    const int LOGITS = BB * NCC;
    const int ALPHAS = TT * BB * PP;
    const int BETAS  = BB * TT;
    int write_alphas = (out_size >= LOGITS + ALPHAS);
    int write_betas  = (out_size >= LOGITS + ALPHAS + BETAS);

    mega_kernel<<<148, 256>>>(videos, h1, c1, h2, c2, spatialBias, temporalBias,
                              W_h2p, b_h2p, W_sC21, b_sC21, W_h21, b_h21,
                              W_tC21, b_tC21, Wih1, Whh1, bih1, bhh1,
                              Wih2, Whh2, bih2, bhh2, W_fc, b_fc,
                              out, write_alphas, write_betas);
}

// round 13
// speedup vs baseline: 3.1401x; 1.2326x over previous
#include <cuda_runtime.h>
#include <math.h>
#include <float.h>

#define BB  32
#define TT  20
#define CC  512
#define PP  196
#define HH  1024
#define NCC 101

#define NSEG1 12          // cell1: K=512(4 segs of 128) + 1024(8 segs)
#define NSEG2 16          // cell2: K=1024+1024
#define NTHR  512

typedef unsigned long long ull;

// ---------------- scratch ----------------
__device__ float g_sA2[TT * BB * PP];
__device__ float g_alogits[BB * 208];
__device__ float g_alphas[TT * BB * PP];
__device__ float g_h1T[2][HH * BB];
__device__ float g_h2T[2][HH * BB];
__device__ float g_h2BH[BB * HH];
__device__ float g_c1T[HH * BB];
__device__ float g_c2T[HH * BB];
__device__ float g_YT[CC * BB];
__device__ float g_betas[TT * BB];
__device__ float g_outs[TT * BB * NCC];
__device__ float g_part1[NSEG1][HH * 4 * BB];
__device__ float g_part2[NSEG2][HH * 4 * BB];

__device__ volatile unsigned g_bar_gen;
__device__ unsigned g_bar_cnt;

__device__ __forceinline__ float sigm(float x) { return 1.f / (1.f + expf(-x)); }

__device__ __forceinline__ void fma2(ull& d, ull a, ull b) {
    asm("fma.rn.f32x2 %0, %1, %2, %0;" : "+l"(d) : "l"(a), "l"(b));
}
__device__ __forceinline__ ull dup2(float a) {
    ull r; asm("mov.b64 %0, {%1, %1};" : "=l"(r) : "f"(a)); return r;
}
__device__ __forceinline__ void unpack2(ull v, float& lo, float& hi) {
    asm("mov.b64 {%0, %1}, %2;" : "=f"(lo), "=f"(hi) : "l"(v));
}

__device__ __forceinline__ void grid_sync_dev() {
    __syncthreads();
    if (threadIdx.x == 0) {
        unsigned gen = g_bar_gen;
        __threadfence();
        if (atomicAdd(&g_bar_cnt, 1u) == gridDim.x - 1) {
            g_bar_cnt = 0;
            __threadfence();
            g_bar_gen = gen + 1;
        } else {
            while (g_bar_gen == gen) { }
            __threadfence();
        }
    }
    __syncthreads();
}

// ---------------- GEMM worker (128 threads), unit = 16 jj rows x 128 k ----------------
// unit: (jjblock 0..63) | (seg<<6). as_: 1024 floats [k*32+b]; ws_: 2048 floats [row*64+e]
__device__ __forceinline__ void gemm_worker(
    int htid,
    const float* __restrict__ actA, const float* __restrict__ WA, int KA,
    const float* __restrict__ actB, const float* __restrict__ WB,
    float* __restrict__ part, int unit,
    float* __restrict__ as_, float* __restrict__ ws_)
{
    const int lane = htid & 31, wid = htid >> 5;
    const int jjb = (unit & 63) * 16;
    const int seg = unit >> 6;
    const int nA = KA >> 7;

    const float* act; const float* W; int k0, Kw;
    if (seg < nA) { act = actA; W = WA; k0 = seg << 7; Kw = KA; }
    else          { act = actB; W = WB; k0 = (seg - nA) << 7; Kw = HH; }

    const int e = htid & 63;
    const int kh = htid >> 6;
    const int g = e & 3;
    const int locjj = e >> 2;
    const float* wsrc = W + (size_t)(g * HH + jjb + locjj) * Kw + k0 + kh * 16;
    const float4* asrc = (const float4*)(act + (size_t)k0 * BB);

    ull acc[8];
#pragma unroll
    for (int i = 0; i < 8; i++) acc[i] = 0ull;
    const int rowbase = wid * 16;

    float4 w4[4], a4[2];
#pragma unroll
    for (int i = 0; i < 4; i++) w4[i] = ((const float4*)wsrc)[i];
    a4[0] = asrc[htid]; a4[1] = asrc[htid + 128];

    const int ntiles = 128 / 32;   // 4
#pragma unroll
    for (int tile = 0; tile < ntiles; tile++) {
        __syncthreads();
        ((float4*)as_)[htid] = a4[0];
        ((float4*)as_)[htid + 128] = a4[1];
#pragma unroll
        for (int i = 0; i < 4; i++) {
            ws_[(kh * 16 + 4 * i + 0) * 64 + e] = w4[i].x;
            ws_[(kh * 16 + 4 * i + 1) * 64 + e] = w4[i].y;
            ws_[(kh * 16 + 4 * i + 2) * 64 + e] = w4[i].z;
            ws_[(kh * 16 + 4 * i + 3) * 64 + e] = w4[i].w;
        }
        __syncthreads();
        if (tile + 1 < ntiles) {
            const float4* wn = (const float4*)(wsrc + (tile + 1) * 32);
#pragma unroll
            for (int i = 0; i < 4; i++) w4[i] = wn[i];
            const float4* an = asrc + (tile + 1) * 256;
            a4[0] = an[htid]; a4[1] = an[htid + 128];
        }
#pragma unroll
        for (int k = 0; k < 32; k++) {
            ull a2 = dup2(as_[k * 32 + lane]);
#pragma unroll
            for (int j = 0; j < 4; j++) {
                ulonglong2 wv = *(const ulonglong2*)&ws_[k * 64 + rowbase + 4 * j];
                fma2(acc[2 * j], a2, wv.x);
                fma2(acc[2 * j + 1], a2, wv.y);
            }
        }
    }

#pragma unroll
    for (int j = 0; j < 4; j++) {
        float f0, f1, f2, f3;
        unpack2(acc[2 * j], f0, f1);
        unpack2(acc[2 * j + 1], f2, f3);
        int jj = jjb + wid * 4 + j;
        float* dst = part + (size_t)seg * (HH * 4 * BB) + (size_t)jj * 4 * BB + lane;
        dst[0 * BB] = f0; dst[1 * BB] = f1; dst[2 * BB] = f2; dst[3 * BB] = f3;
    }
}

// ---------------- persistent mega-kernel ----------------
__global__ void __launch_bounds__(NTHR, 1) mega_kernel(
    const float* __restrict__ videos,
    const float* __restrict__ h1, const float* __restrict__ c1,
    const float* __restrict__ h2, const float* __restrict__ c2,
    const float* __restrict__ spatialBias, const float* __restrict__ temporalBias,
    const float* __restrict__ W_h2p, const float* __restrict__ b_h2p,
    const float* __restrict__ W_sC21, const float* __restrict__ b_sC21,
    const float* __restrict__ W_h21, const float* __restrict__ b_h21,
    const float* __restrict__ W_tC21, const float* __restrict__ b_tC21,
    const float* __restrict__ Wih1, const float* __restrict__ Whh1,
    const float* __restrict__ bih1, const float* __restrict__ bhh1,
    const float* __restrict__ Wih2, const float* __restrict__ Whh2,
    const float* __restrict__ bih2, const float* __restrict__ bhh2,
    const float* __restrict__ W_fc, const float* __restrict__ b_fc,
    float* __restrict__ out, int write_alphas, int write_betas)
{
    // 48KB arena: gemm workers own it during D/F; other phases overlay it.
    __shared__ __align__(16) float s_arena[4 * (1024 + 2048)];   // 49152 B
    float* s_red = s_arena;               // 512
    float* s_al  = s_arena + 512;         // 196 (float4-aligned: 2048B)
    float* s_h2  = s_arena + 1024;        // 1024 (4096B offset, float4-aligned)
    float* s_wsc = s_arena + 2048;        // 512
    float* s_bw  = s_arena + 2560;        // 20

    const int tid = threadIdx.x, lane = tid & 31, wid = tid >> 5;
    const int NBK = gridDim.x;
    const int worker = tid >> 7, htid = tid & 127;
    float* w_as = s_arena + worker * 3072;
    float* w_ws = s_arena + worker * 3072 + 1024;

    const int LOGITS = BB * NCC;
    const int ALPHAS = TT * BB * PP;

    // ---- init ----
    for (int vb = blockIdx.x; vb < 64; vb += NBK) {
        int i = vb * NTHR + tid;
        int h = i >> 5, b = i & 31;
        g_h1T[0][i] = h1[h];
        g_c1T[i]    = c1[h];
        g_h2T[0][i] = h2[h];
        g_c2T[i]    = c2[h];
        g_h2BH[b * HH + h] = h2[h];
    }

    // ---- precompute sA2: 2 (b,t) per block-pass ----
    for (int i = tid; i < CC; i += NTHR) s_wsc[i] = W_sC21[i];
    __syncthreads();
    for (int vb = blockIdx.x; vb < 320; vb += NBK) {
        int sub = tid >> 8;                 // 0/1
        int p = tid & 255;
        int bt = vb * 2 + sub;              // 0..639
        int b = bt >> 5 >= 0 ? bt / TT : 0; // b = bt/TT
        b = bt / TT;
        int t = bt % TT;
        if (p < PP) {
            const float* vbp = videos + (((size_t)b * TT + t) * CC) * PP + p;
            float acc = 0.f;
#pragma unroll 4
            for (int c = 0; c < CC; c++) acc = fmaf(vbp[(size_t)c * PP], s_wsc[c], acc);
            g_sA2[(t * BB + b) * PP + p] = acc + b_sC21[0];
        }
    }
    grid_sync_dev();

    for (int t = 0; t < TT; t++) {
        float* h1_in  = g_h1T[t & 1];
        float* h1_out = g_h1T[(t + 1) & 1];
        float* h2_in  = g_h2T[t & 1];
        float* h2_out = g_h2T[(t + 1) & 1];

        // ---- Phase A: attention logits + fc(prev h2) ----
        for (int vb = blockIdx.x; vb < 256; vb += NBK) {
            int b = vb >> 3, chunk = vb & 7;
            if (tid < 256) ((float4*)s_h2)[tid] = ((const float4*)(g_h2BH + b * HH))[tid];
            __syncthreads();
            const float4* h2v = (const float4*)s_h2;
            if (chunk < 7) {
                for (int sub = wid; sub < 28; sub += 16) {
                    int p = chunk * 28 + sub;
                    const float4* wr = (const float4*)(W_h2p + (size_t)p * HH);
                    float s = 0.f;
                    for (int i = lane; i < HH / 4; i += 32) {
                        float4 w = wr[i]; float4 a = h2v[i];
                        s = fmaf(a.x, w.x, s); s = fmaf(a.y, w.y, s);
                        s = fmaf(a.z, w.z, s); s = fmaf(a.w, w.w, s);
                    }
                    for (int o = 16; o; o >>= 1) s += __shfl_down_sync(0xffffffffu, s, o);
                    if (lane == 0)
                        g_alogits[b * 208 + p] = s + b_h2p[p] + g_sA2[(t * BB + b) * PP + p] + spatialBias[p];
                }
            } else if (t > 0) {
                for (int nc = wid; nc < NCC; nc += 16) {
                    const float4* wr = (const float4*)(W_fc + (size_t)nc * HH);
                    float s = 0.f;
                    for (int i = lane; i < HH / 4; i += 32) {
                        float4 w = wr[i]; float4 a = h2v[i];
                        s = fmaf(a.x, w.x, s); s = fmaf(a.y, w.y, s);
                        s = fmaf(a.z, w.z, s); s = fmaf(a.w, w.w, s);
                    }
                    for (int o = 16; o; o >>= 1) s += __shfl_down_sync(0xffffffffu, s, o);
                    if (lane == 0) g_outs[((t - 1) * BB + b) * NCC + nc] = s + b_fc[nc];
                }
            }
            __syncthreads();
        }
        grid_sync_dev();

        // ---- Phase B: softmax + Y gather (warp handles 4 c-rows, MLP=4) ----
        for (int vb = blockIdx.x; vb < 256; vb += NBK) {
            int b = vb >> 3, cs = vb & 7;
            float v = -FLT_MAX;
            if (tid < 256) {
                v = (tid < PP) ? g_alogits[b * 208 + tid] : -FLT_MAX;
                s_red[tid] = v;
            }
            __syncthreads();
            for (int s = 128; s > 0; s >>= 1) { if (tid < s) s_red[tid] = fmaxf(s_red[tid], s_red[tid + s]); __syncthreads(); }
            float m = s_red[0]; __syncthreads();
            float e = (tid < PP) ? expf(v - m) : 0.f;
            if (tid < 256) s_red[tid] = e;
            __syncthreads();
            for (int s = 128; s > 0; s >>= 1) { if (tid < s) s_red[tid] += s_red[tid + s]; __syncthreads(); }
            float inv = 1.f / s_red[0];
            if (tid < PP) {
                float a = e * inv;
                s_al[tid] = a;
                if (cs == 0) g_alphas[(t * BB + b) * PP + tid] = a;
            }
            __syncthreads();
            const float4* al4 = (const float4*)s_al;
            const float* vbp = videos + ((size_t)(b * TT + t) * CC) * PP;
            int c = cs * 64 + wid * 4;
            const float4* vr0 = (const float4*)(vbp + (size_t)(c + 0) * PP);
            const float4* vr1 = (const float4*)(vbp + (size_t)(c + 1) * PP);
            const float4* vr2 = (const float4*)(vbp + (size_t)(c + 2) * PP);
            const float4* vr3 = (const float4*)(vbp + (size_t)(c + 3) * PP);
            float s0 = 0.f, s1 = 0.f, s2 = 0.f, s3 = 0.f;
            for (int i = lane; i < 49; i += 32) {
                float4 a = al4[i];
                float4 v0 = vr0[i], v1 = vr1[i], v2 = vr2[i], v3 = vr3[i];
                s0 = fmaf(a.x, v0.x, s0); s0 = fmaf(a.y, v0.y, s0); s0 = fmaf(a.z, v0.z, s0); s0 = fmaf(a.w, v0.w, s0);
                s1 = fmaf(a.x, v1.x, s1); s1 = fmaf(a.y, v1.y, s1); s1 = fmaf(a.z, v1.z, s1); s1 = fmaf(a.w, v1.w, s1);
                s2 = fmaf(a.x, v2.x, s2); s2 = fmaf(a.y, v2.y, s2); s2 = fmaf(a.z, v2.z, s2); s2 = fmaf(a.w, v2.w, s2);
                s3 = fmaf(a.x, v3.x, s3); s3 = fmaf(a.y, v3.y, s3); s3 = fmaf(a.z, v3.z, s3); s3 = fmaf(a.w, v3.w, s3);
            }
            for (int o = 16; o; o >>= 1) {
                s0 += __shfl_down_sync(0xffffffffu, s0, o);
                s1 += __shfl_down_sync(0xffffffffu, s1, o);
                s2 += __shfl_down_sync(0xffffffffu, s2, o);
                s3 += __shfl_down_sync(0xffffffffu, s3, o);
            }
            if (lane == 0) {
                g_YT[(c + 0) * BB + b] = s0;
                g_YT[(c + 1) * BB + b] = s1;
                g_YT[(c + 2) * BB + b] = s2;
                g_YT[(c + 3) * BB + b] = s3;
            }
            __syncthreads();
        }
        grid_sync_dev();

        // ---- Phase D: gemm1 (192 super-units of 4) + beta on last block ----
        for (int su = blockIdx.x; su < NSEG1 * 64 / 4; su += NBK) {
            gemm_worker(htid, g_YT, Wih1, CC, h1_in, Whh1,
                        &g_part1[0][0], su * 4 + worker, w_as, w_ws);
        }
        if (blockIdx.x == NBK - 1) {
            // beta: warp w -> b = 2w, 2w+1
            for (int r = 0; r < 2; r++) {
                int b = wid * 2 + r;
                const float* h2r = g_h2BH + b * HH;
                float s = 0.f;
                for (int h = lane; h < HH; h += 32) s = fmaf(h2r[h], W_h21[h], s);
                for (int cc = lane; cc < CC; cc += 32) s = fmaf(g_YT[cc * BB + b], W_tC21[cc], s);
                for (int o = 16; o; o >>= 1) s += __shfl_down_sync(0xffffffffu, s, o);
                if (lane == 0)
                    g_betas[t * BB + b] = s + b_h21[0] + b_tC21[0] + temporalBias[0];
            }
        }
        grid_sync_dev();

        // ---- Phase E: epilogue cell 1 ----
        {
            int i = blockIdx.x * NTHR + tid;
            if (i < HH * BB) {
                int jj = i >> 5, b = i & 31;
                float gv[4];
#pragma unroll
                for (int g = 0; g < 4; g++) {
                    float s = bih1[g * HH + jj] + bhh1[g * HH + jj];
#pragma unroll
                    for (int sg = 0; sg < NSEG1; sg++)
                        s += g_part1[sg][(jj * 4 + g) * BB + b];
                    gv[g] = s;
                }
                int idx = jj * BB + b;
                float cn = sigm(gv[1]) * g_c1T[idx] + sigm(gv[0]) * tanhf(gv[2]);
                g_c1T[idx] = cn;
                h1_out[idx] = sigm(gv[3]) * tanhf(cn);
            }
        }
        grid_sync_dev();

        // ---- Phase F: gemm2 (256 super-units) ----
        for (int su = blockIdx.x; su < NSEG2 * 64 / 4; su += NBK) {
            gemm_worker(htid, h1_out, Wih2, HH, h2_in, Whh2,
                        &g_part2[0][0], su * 4 + worker, w_as, w_ws);
        }
        grid_sync_dev();

        // ---- Phase G: epilogue cell 2 ----
        {
            int i = blockIdx.x * NTHR + tid;
            if (i < HH * BB) {
                int jj = i >> 5, b = i & 31;
                float gv[4];
#pragma unroll
                for (int g = 0; g < 4; g++) {
                    float s = bih2[g * HH + jj] + bhh2[g * HH + jj];
#pragma unroll
                    for (int sg = 0; sg < NSEG2; sg++)
                        s += g_part2[sg][(jj * 4 + g) * BB + b];
                    gv[g] = s;
                }
                int idx = jj * BB + b;
                float cn = sigm(gv[1]) * g_c2T[idx] + sigm(gv[0]) * tanhf(gv[2]);
                float hn = sigm(gv[3]) * tanhf(cn);
                g_c2T[idx] = cn;
                h2_out[idx] = hn;
                g_h2BH[b * HH + jj] = hn;
            }
        }
        grid_sync_dev();
    }

    // ---- Final ----
    {
        const int NCOPY4 = (TT * BB * PP) / 4;                 // 31360
        const int NVB_FIN = 32 + (NCOPY4 + NTHR - 1) / NTHR;   // 32 + 62
        for (int vb = blockIdx.x; vb < NVB_FIN; vb += NBK) {
            if (vb < 32) {
                int b = vb;
                for (int i = tid; i < HH; i += NTHR) s_h2[i] = g_h2BH[b * HH + i];
                __syncthreads();
                for (int nc = wid; nc < NCC; nc += 16) {
                    const float* wr = W_fc + (size_t)nc * HH;
                    float s = 0.f;
                    for (int h = lane; h < HH; h += 32) s = fmaf(s_h2[h], wr[h], s);
                    for (int o = 16; o; o >>= 1) s += __shfl_down_sync(0xffffffffu, s, o);
                    if (lane == 0) g_outs[((TT - 1) * BB + b) * NCC + nc] = s + b_fc[nc];
                }
                __syncthreads();
                if (tid == 0) {
                    float m = -FLT_MAX;
                    for (int tt = 0; tt < TT; tt++) m = fmaxf(m, g_betas[tt * BB + b]);
                    float s = 0.f;
                    for (int tt = 0; tt < TT; tt++) { float e = expf(g_betas[tt * BB + b] - m); s_bw[tt] = e; s += e; }
                    float inv = 1.f / s;
                    for (int tt = 0; tt < TT; tt++) {
                        s_bw[tt] *= inv;
                        if (write_betas) out[LOGITS + ALPHAS + b * TT + tt] = s_bw[tt];
                    }
                }
                __syncthreads();
                for (int nc = tid; nc < NCC; nc += NTHR) {
                    float s = 0.f;
                    for (int tt = 0; tt < TT; tt++) s = fmaf(s_bw[tt], g_outs[(tt * BB + b) * NCC + nc], s);
                    out[b * NCC + nc] = s;
                }
                __syncthreads();
            } else if (write_alphas) {
                int i = (vb - 32) * NTHR + tid;
                if (i < NCOPY4)
                    ((float4*)(out + LOGITS))[i] = ((const float4*)g_alphas)[i];
            }
        }
    }
}

// ---------------- launch ----------------
extern "C" void kernel_launch(void* const* d_in, const int* in_sizes, int n_in,
                              void* d_out, int out_size) {
    const float* videos       = (const float*)d_in[0];
    const float* h1           = (const float*)d_in[1];
    const float* c1           = (const float*)d_in[2];
    const float* h2           = (const float*)d_in[3];
    const float* c2           = (const float*)d_in[4];
    const float* spatialBias  = (const float*)d_in[5];
    const float* temporalBias = (const float*)d_in[6];
    const float* W_h2p        = (const float*)d_in[7];
    const float* b_h2p        = (const float*)d_in[8];
    const float* W_sC21       = (const float*)d_in[9];
    const float* b_sC21       = (const float*)d_in[10];
    const float* W_h21        = (const float*)d_in[11];
    const float* b_h21        = (const float*)d_in[12];
    const float* W_tC21       = (const float*)d_in[13];
    const float* b_tC21       = (const float*)d_in[14];
    const float* Wih1         = (const float*)d_in[15];
    const float* Whh1         = (const float*)d_in[16];
    const float* bih1         = (const float*)d_in[17];
    const float* bhh1         = (const float*)d_in[18];
    const float* Wih2         = (const float*)d_in[19];
    const float* Whh2         = (const float*)d_in[20];
    const float* bih2         = (const float*)d_in[21];
    const float* bhh2         = (const float*)d_in[22];
    const float* W_fc         = (const float*)d_in[23];
    const float* b_fc         = (const float*)d_in[24];

    float* out = (float*)d_out;
    const int LOGITS = BB * NCC;
    const int ALPHAS = TT * BB * PP;
    const int BETAS  = BB * TT;
    int write_alphas = (out_size >= LOGITS + ALPHAS);
    int write_betas  = (out_size >= LOGITS + ALPHAS + BETAS);

    mega_kernel<<<148, NTHR>>>(videos, h1, c1, h2, c2, spatialBias, temporalBias,
                               W_h2p, b_h2p, W_sC21, b_sC21, W_h21, b_h21,
                               W_tC21, b_tC21, Wih1, Whh1, bih1, bhh1,
                               Wih2, Whh2, bih2, bhh2, W_fc, b_fc,
                               out, write_alphas, write_betas);
}